// round 2
// baseline (speedup 1.0000x reference)
#include <cuda_runtime.h>
#include <cuda_bf16.h>
#include <cstdint>

// Problem constants
#define B_WIN 512
#define NTOK  256
#define CDIM  256
#define HEADS 8
#define DHEAD 32
#define NW    256
#define MROWS (B_WIN * NTOK)   // 131072

// ---------------------------------------------------------------------------
// Scratch
// ---------------------------------------------------------------------------
__device__ float g_Q[B_WIN * HEADS * NTOK * DHEAD];
__device__ float g_K[B_WIN * HEADS * NTOK * DHEAD];
__device__ float g_V[B_WIN * HEADS * NTOK * DHEAD];
__device__ float g_O[B_WIN * NTOK * CDIM];

// ---------------------------------------------------------------------------
// tf32 helpers
// ---------------------------------------------------------------------------
__device__ __forceinline__ uint32_t f2tf32(float x) {
    uint32_t r;
    asm("cvt.rna.tf32.f32 %0, %1;" : "=r"(r) : "f"(x));
    return r;
}

__device__ __forceinline__ void mma_m16n8k8(float* c, const uint32_t* a,
                                            const uint32_t* b) {
    asm("mma.sync.aligned.m16n8k8.row.col.f32.tf32.tf32.f32 "
        "{%0,%1,%2,%3}, {%4,%5,%6,%7}, {%8,%9}, {%0,%1,%2,%3};"
        : "+f"(c[0]), "+f"(c[1]), "+f"(c[2]), "+f"(c[3])
        : "r"(a[0]), "r"(a[1]), "r"(a[2]), "r"(a[3]), "r"(b[0]), "r"(b[1]));
}

// split x into tf32 hi + tf32 lo
__device__ __forceinline__ void split_tf32(float x, uint32_t& h, uint32_t& l) {
    h = f2tf32(x);
    l = f2tf32(x - __uint_as_float(h));
}

// ---------------------------------------------------------------------------
// 3xTF32 GEMM: C = A(M x 256) @ W(256 x Ncols) + bias.
// CTA 128x128, BK=32, 8 warps as 4(M) x 2(N), warp tile 32x64.
// SMEM layout (per tile): [row][group(s*4+c)] of float4 {hi(c),hi(c+4),lo(c),lo(c+4)}
// row stride 76 floats (uniform bank histogram for LDS.128).
// MODE 0: plain row-major. MODE 1: Q scatter (b,h,n,d). MODE 2: KV split scatter.
// ---------------------------------------------------------------------------
#define GS 76
#define GEMM_SMEM_FLOATS (128 * GS * 2)
#define GEMM_SMEM_BYTES  (GEMM_SMEM_FLOATS * 4)

template<int MODE>
__global__ void __launch_bounds__(256, 2) gemm_tc(
    const float* __restrict__ A, const float* __restrict__ W,
    const float* __restrict__ bias,
    float* __restrict__ out0, float* __restrict__ out1, int Ncols)
{
    extern __shared__ float sm[];
    float* As = sm;             // [128][GS]
    float* Bs = sm + 128 * GS;  // [128 n][GS]

    const int t    = threadIdx.x;
    const int row0 = blockIdx.y * 128;
    const int col0 = blockIdx.x * 128;

    // ---- global loaders ----
    // A: thread covers row (t>>1), cols half*16 .. +15 of the 32-col stage tile
    const int arow  = t >> 1;
    const int ahalf = t & 1;
    const float* Ap = A + (size_t)(row0 + arow) * 256 + ahalf * 16;

    // B: pair id = t + 256*i : kp = id>>5 in 0..15, n4 = id&31
    //    k = (kp>>2)*8 + (kp&3); loads rows k and k+4, cols n4*4..+3
    int kp0 = t >> 5,        n40 = t & 31;
    int kp1 = (t + 256) >> 5, n41 = t & 31;
    const int k0 = (kp0 >> 2) * 8 + (kp0 & 3);
    const int k1 = (kp1 >> 2) * 8 + (kp1 & 3);
    const float* Bp0 = W + (size_t)k0 * Ncols + col0 + n40 * 4;
    const float* Bp1 = W + (size_t)k1 * Ncols + col0 + n41 * 4;

    float4 la[4], lb[4];

    auto load_stage = [&](int st) {
#pragma unroll
        for (int i = 0; i < 4; ++i)
            la[i] = *(const float4*)(Ap + st * 32 + i * 4);
        lb[0] = *(const float4*)(Bp0 + (size_t)(st * 32) * Ncols);
        lb[1] = *(const float4*)(Bp0 + (size_t)(st * 32 + 4) * Ncols);
        lb[2] = *(const float4*)(Bp1 + (size_t)(st * 32) * Ncols);
        lb[3] = *(const float4*)(Bp1 + (size_t)(st * 32 + 4) * Ncols);
    };

    auto store_stage = [&]() {
        // A: groups for s = ahalf*2 + sb
#pragma unroll
        for (int sb = 0; sb < 2; ++sb) {
            const int s = ahalf * 2 + sb;
            float va[4], vb[4];
            *(float4*)va = la[2 * sb];       // cols 8s .. 8s+3   (c, h=0)
            *(float4*)vb = la[2 * sb + 1];   // cols 8s+4 .. 8s+7 (c, h=1)
#pragma unroll
            for (int c = 0; c < 4; ++c) {
                uint32_t h0, l0, h1, l1;
                split_tf32(va[c], h0, l0);
                split_tf32(vb[c], h1, l1);
                float4 gq;
                gq.x = __uint_as_float(h0); gq.y = __uint_as_float(h1);
                gq.z = __uint_as_float(l0); gq.w = __uint_as_float(l1);
                *(float4*)&As[arow * GS + (s * 4 + c) * 4] = gq;
            }
        }
        // B: two (k,k+4) row pairs
#pragma unroll
        for (int i = 0; i < 2; ++i) {
            const int kp = i ? kp1 : kp0;
            const int n4 = i ? n41 : n40;
            const int s = kp >> 2, c = kp & 3;
            float wk[4], wk4[4];
            *(float4*)wk  = lb[2 * i];
            *(float4*)wk4 = lb[2 * i + 1];
#pragma unroll
            for (int ni = 0; ni < 4; ++ni) {
                uint32_t h0, l0, h1, l1;
                split_tf32(wk[ni], h0, l0);
                split_tf32(wk4[ni], h1, l1);
                float4 gq;
                gq.x = __uint_as_float(h0); gq.y = __uint_as_float(h1);
                gq.z = __uint_as_float(l0); gq.w = __uint_as_float(l1);
                *(float4*)&Bs[(n4 * 4 + ni) * GS + (s * 4 + c) * 4] = gq;
            }
        }
    };

    // ---- compute mapping ----
    const int warp = t >> 5, lane = t & 31;
    const int warpM = warp >> 1, warpN = warp & 1;
    const int m0 = warpM * 32, n0 = warpN * 64;
    const int g = lane >> 2, c = lane & 3;

    float acc[2][8][4];
#pragma unroll
    for (int mt = 0; mt < 2; ++mt)
#pragma unroll
        for (int j = 0; j < 8; ++j)
#pragma unroll
            for (int r = 0; r < 4; ++r) acc[mt][j][r] = 0.f;

    load_stage(0);

    for (int st = 0; st < 8; ++st) {
        store_stage();
        __syncthreads();
        if (st < 7) load_stage(st + 1);

#pragma unroll
        for (int s = 0; s < 4; ++s) {
            uint32_t aH[2][4], aL[2][4];
#pragma unroll
            for (int mt = 0; mt < 2; ++mt) {
                uint4 q = *(const uint4*)&As[(m0 + mt * 16 + g) * GS + (s * 4 + c) * 4];
                uint4 r = *(const uint4*)&As[(m0 + mt * 16 + 8 + g) * GS + (s * 4 + c) * 4];
                aH[mt][0] = q.x; aH[mt][1] = r.x; aH[mt][2] = q.y; aH[mt][3] = r.y;
                aL[mt][0] = q.z; aL[mt][1] = r.z; aL[mt][2] = q.w; aL[mt][3] = r.w;
            }
#pragma unroll
            for (int j = 0; j < 8; ++j) {
                uint4 u = *(const uint4*)&Bs[(n0 + j * 8 + g) * GS + (s * 4 + c) * 4];
                uint32_t bH[2] = {u.x, u.y};
                uint32_t bL[2] = {u.z, u.w};
#pragma unroll
                for (int mt = 0; mt < 2; ++mt) {
                    mma_m16n8k8(acc[mt][j], aH[mt], bH);
                    mma_m16n8k8(acc[mt][j], aH[mt], bL);
                    mma_m16n8k8(acc[mt][j], aL[mt], bH);
                }
            }
        }
        __syncthreads();
    }

    // ---- epilogue ----
#pragma unroll
    for (int j = 0; j < 8; ++j) {
        const int cg = col0 + n0 + j * 8 + 2 * c;
        const float b0 = __ldg(&bias[cg]);
        const float b1 = __ldg(&bias[cg + 1]);
#pragma unroll
        for (int mt = 0; mt < 2; ++mt) {
#pragma unroll
            for (int half = 0; half < 2; ++half) {
                const int row = row0 + m0 + mt * 16 + half * 8 + g;
                float2 v;
                v.x = acc[mt][j][half * 2 + 0] + b0;
                v.y = acc[mt][j][half * 2 + 1] + b1;
                if (MODE == 0) {
                    *(float2*)&out0[(size_t)row * Ncols + cg] = v;
                } else {
                    int cc = (MODE == 2) ? (cg & 255) : cg;
                    float* dst = (MODE == 2 && cg >= 256) ? out1 : out0;
                    const int b = row >> 8, n = row & 255;
                    const int head = cc >> 5, dd = cc & 31;
                    size_t idx = (((size_t)(b * HEADS + head) * NTOK + n) << 5) + dd;
                    *(float2*)&dst[idx] = v;
                }
            }
        }
    }
}

// ---------------------------------------------------------------------------
// Attention (unchanged): one CTA per (b,h).
// ---------------------------------------------------------------------------
#define ATT_SMEM ((8192 + 8192 + 32 * 260 + 8 * 2048) * 4)

__global__ void __launch_bounds__(256, 1) attn_kernel(
    const float* __restrict__ Q, const float* __restrict__ K,
    const float* __restrict__ V, const float* __restrict__ mask,
    float* __restrict__ O)
{
    extern __shared__ float sm[];
    float* qs = sm;
    float* kT = sm + 8192;
    float* vT = sm + 16384;
    float* ps = sm + 16384 + 32 * 260;

    const int bh = blockIdx.x;
    const int b  = bh >> 3;
    const int h  = bh & 7;
    const int w  = b & (NW - 1);
    const size_t base = (size_t)bh * (NTOK * DHEAD);
    const int tid = threadIdx.x;

    {
        const float4* Q4 = (const float4*)(Q + base);
        const float4* K4 = (const float4*)(K + base);
        const float4* V4 = (const float4*)(V + base);
#pragma unroll
        for (int ii = 0; ii < 8; ++ii) {
            const int i = tid + ii * 256;
            const int n = i >> 3;
            const int d0 = (i & 7) << 2;
            float4 qv = Q4[i];
            ((float4*)qs)[i] = qv;
            float4 kv = K4[i];
            kT[(d0 + 0) * 256 + n] = kv.x;
            kT[(d0 + 1) * 256 + n] = kv.y;
            kT[(d0 + 2) * 256 + n] = kv.z;
            kT[(d0 + 3) * 256 + n] = kv.w;
            float4 vv = V4[i];
            vT[(d0 + 0) * 260 + n] = vv.x;
            vT[(d0 + 1) * 260 + n] = vv.y;
            vT[(d0 + 2) * 260 + n] = vv.z;
            vT[(d0 + 3) * 260 + n] = vv.w;
        }
    }
    __syncthreads();

    const int warp = tid >> 5, lane = tid & 31;
    float* psw = ps + warp * 2048;
    const float* maskw = mask + (size_t)w * (NTOK * NTOK);
    const float scale = 0.17677669529663687f;
    float* Obase = O + ((size_t)b * NTOK) * CDIM + h * DHEAD + lane;

    for (int pass = 0; pass < 4; ++pass) {
        const int row0 = warp * 32 + pass * 8;

        float mrg[8][8];
#pragma unroll
        for (int r = 0; r < 8; ++r) {
            const float* mp = maskw + (size_t)(row0 + r) * NTOK + lane * 8;
            float4 a = *(const float4*)mp;
            float4 cc = *(const float4*)(mp + 4);
            mrg[r][0] = a.x; mrg[r][1] = a.y; mrg[r][2] = a.z; mrg[r][3] = a.w;
            mrg[r][4] = cc.x; mrg[r][5] = cc.y; mrg[r][6] = cc.z; mrg[r][7] = cc.w;
        }

        float s[8][8];
#pragma unroll
        for (int r = 0; r < 8; ++r)
#pragma unroll
            for (int i = 0; i < 8; ++i) s[r][i] = 0.f;

#pragma unroll 8
        for (int d = 0; d < 32; ++d) {
            float kf[8];
            *(float4*)&kf[0] = *(const float4*)&kT[d * 256 + lane * 8];
            *(float4*)&kf[4] = *(const float4*)&kT[d * 256 + lane * 8 + 4];
#pragma unroll
            for (int r = 0; r < 8; ++r) {
                const float qv = qs[(row0 + r) * 32 + d];
#pragma unroll
                for (int i = 0; i < 8; ++i)
                    s[r][i] = fmaf(qv, kf[i], s[r][i]);
            }
        }

        float rinv[8];
#pragma unroll
        for (int r = 0; r < 8; ++r) {
            float mx = -3.4e38f;
#pragma unroll
            for (int i = 0; i < 8; ++i) {
                const float v = fmaf(s[r][i], scale, mrg[r][i]);
                s[r][i] = v;
                mx = fmaxf(mx, v);
            }
#pragma unroll
            for (int off = 16; off; off >>= 1)
                mx = fmaxf(mx, __shfl_xor_sync(0xffffffffu, mx, off));
            float sum = 0.f;
#pragma unroll
            for (int i = 0; i < 8; ++i) {
                const float e = __expf(s[r][i] - mx);
                sum += e;
                psw[r * 256 + lane * 8 + i] = e;
            }
#pragma unroll
            for (int off = 16; off; off >>= 1)
                sum += __shfl_xor_sync(0xffffffffu, sum, off);
            rinv[r] = 1.0f / sum;
        }
        __syncwarp();

        float o[8] = {0.f, 0.f, 0.f, 0.f, 0.f, 0.f, 0.f, 0.f};
#pragma unroll 4
        for (int jc = 0; jc < 256; jc += 4) {
            const float4 vv = *(const float4*)&vT[lane * 260 + jc];
#pragma unroll
            for (int r = 0; r < 8; ++r) {
                const float4 pv = *(const float4*)&psw[r * 256 + jc];
                float a2 = fmaf(pv.x, vv.x, fmaf(pv.y, vv.y,
                           fmaf(pv.z, vv.z, pv.w * vv.w)));
                o[r] += a2;
            }
        }
#pragma unroll
        for (int r = 0; r < 8; ++r)
            Obase[(size_t)(row0 + r) * CDIM] = o[r] * rinv[r];
        __syncwarp();
    }
}

// ---------------------------------------------------------------------------
// Host launcher
// ---------------------------------------------------------------------------
extern "C" void kernel_launch(void* const* d_in, const int* in_sizes, int n_in,
                              void* d_out, int out_size)
{
    const float* x    = (const float*)d_in[0];
    const float* mask = (const float*)d_in[1];
    const float* Wq   = (const float*)d_in[2];
    const float* bq   = (const float*)d_in[3];
    const float* Wkv  = (const float*)d_in[4];
    const float* bkv  = (const float*)d_in[5];
    const float* Wp   = (const float*)d_in[6];
    const float* bp   = (const float*)d_in[7];
    float* out = (float*)d_out;

    void *pQ, *pK, *pV, *pO;
    cudaGetSymbolAddress(&pQ, g_Q);
    cudaGetSymbolAddress(&pK, g_K);
    cudaGetSymbolAddress(&pV, g_V);
    cudaGetSymbolAddress(&pO, g_O);
    float* Qb = (float*)pQ;
    float* Kb = (float*)pK;
    float* Vb = (float*)pV;
    float* Ob = (float*)pO;

    cudaFuncSetAttribute(gemm_tc<0>,
                         cudaFuncAttributeMaxDynamicSharedMemorySize, GEMM_SMEM_BYTES);
    cudaFuncSetAttribute(gemm_tc<1>,
                         cudaFuncAttributeMaxDynamicSharedMemorySize, GEMM_SMEM_BYTES);
    cudaFuncSetAttribute(gemm_tc<2>,
                         cudaFuncAttributeMaxDynamicSharedMemorySize, GEMM_SMEM_BYTES);
    cudaFuncSetAttribute(attn_kernel,
                         cudaFuncAttributeMaxDynamicSharedMemorySize, ATT_SMEM);

    dim3 blk(256);
    gemm_tc<1><<<dim3(2, MROWS / 128), blk, GEMM_SMEM_BYTES>>>(x, Wq, bq, Qb, nullptr, 256);
    gemm_tc<2><<<dim3(4, MROWS / 128), blk, GEMM_SMEM_BYTES>>>(x, Wkv, bkv, Kb, Vb, 512);
    attn_kernel<<<B_WIN * HEADS, blk, ATT_SMEM>>>(Qb, Kb, Vb, mask, Ob);
    gemm_tc<0><<<dim3(2, MROWS / 128), blk, GEMM_SMEM_BYTES>>>(Ob, Wp, bp, out, nullptr, 256);
}